// round 7
// baseline (speedup 1.0000x reference)
#include <cuda_runtime.h>

// circ_layer: out = mm*x + mm + x, mm[b,i] = sum_j x[b,j] * w[(j-i) mod 1024]
// = circular correlation => IDFT( FFT(x_row) * conj(FFT(w)) ), fp32.
//
// Four-step FFT (1024 = 32x32), one warp per FOUR tokens: two complex
// sequences (tok0+i*tok1, tok2+i*tok3) processed simultaneously via packed
// f32x2 (FFMA2/FADD2) ops: R[i]=(re1,re2), I[i]=(im1,im2). All butterflies
// and rotations are element-wise across the two sequences -> no swaps.

static constexpr int WPB  = 4;            // warps per block
static constexpr int TPB  = WPB * 32;
static constexpr int NTOK = 65536;

__device__ __align__(16) float2 g_wc[1024];    // conj(FFT(w))/N, pipeline layout
__device__ __align__(16) float2 g_mtw[1024];   // T[k*32+lane] = e^{-2pi*i*k*lane/1024}

__device__ __forceinline__ int br5(int x) {
    return ((x & 1) << 4) | ((x & 2) << 2) | (x & 4) | ((x & 8) >> 2) | ((x & 16) >> 4);
}

__device__ __forceinline__ float twc(int t) {
    constexpr float C[16] = {
        1.0f,                   0.9807852804032304f,  0.9238795325112867f,  0.8314696123025452f,
        0.7071067811865476f,    0.5555702330196022f,  0.3826834323650898f,  0.1950903220161283f,
        0.0f,                  -0.1950903220161283f, -0.3826834323650898f, -0.5555702330196022f,
       -0.7071067811865476f,   -0.8314696123025452f, -0.9238795325112867f, -0.9807852804032304f };
    return C[t];
}
__device__ __forceinline__ float tws(int t) {
    constexpr float S[16] = {
        0.0f,                   0.1950903220161283f,  0.3826834323650898f,  0.5555702330196022f,
        0.7071067811865476f,    0.8314696123025452f,  0.9238795325112867f,  0.9807852804032304f,
        1.0f,                   0.9807852804032304f,  0.9238795325112867f,  0.8314696123025452f,
        0.7071067811865476f,    0.5555702330196022f,  0.3826834323650898f,  0.1950903220161283f };
    return S[t];
}

// ---------------- packed f32x2 primitives ----------------

struct P { unsigned long long v; };

__device__ __forceinline__ P pk(float lo, float hi) {
    P r; asm("mov.b64 %0, {%1, %2};" : "=l"(r.v) : "f"(lo), "f"(hi)); return r;
}
__device__ __forceinline__ void upk(P a, float& lo, float& hi) {
    asm("mov.b64 {%0, %1}, %2;" : "=f"(lo), "=f"(hi) : "l"(a.v));
}
__device__ __forceinline__ P pbc(float f) { return pk(f, f); }
__device__ __forceinline__ P padd(P a, P b) {
    P r; asm("add.rn.f32x2 %0, %1, %2;" : "=l"(r.v) : "l"(a.v), "l"(b.v)); return r;
}
__device__ __forceinline__ P pmul(P a, P b) {
    P r; asm("mul.rn.f32x2 %0, %1, %2;" : "=l"(r.v) : "l"(a.v), "l"(b.v)); return r;
}
__device__ __forceinline__ P pfma(P a, P b, P c) {   // a*b + c
    P r; asm("fma.rn.f32x2 %0, %1, %2, %3;" : "=l"(r.v) : "l"(a.v), "l"(b.v), "l"(c.v)); return r;
}
__device__ __forceinline__ P psub(P a, P b) {        // a - b
    return pfma(b, pbc(-1.0f), a);
}

// (xr,xi) = (dr,di) * e^{-+2*pi*i*t/32} elementwise over both packed seqs
template<bool INV>
__device__ __forceinline__ void prot(int t, P dr, P di, P& xr, P& xi) {
    if (t == 0)      { xr = dr; xi = di; }
    else if (t == 8) {
        if (!INV) { xr = di;                    xi = pmul(dr, pbc(-1.0f)); }
        else      { xr = pmul(di, pbc(-1.0f)); xi = dr; }
    } else {
        const float c = twc(t), s = tws(t);
        if (!INV) { xr = pfma(dr, pbc(c), pmul(di, pbc(s)));
                    xi = pfma(di, pbc(c), pmul(dr, pbc(-s))); }
        else      { xr = pfma(dr, pbc(c), pmul(di, pbc(-s)));
                    xi = pfma(di, pbc(c), pmul(dr, pbc(s))); }
    }
}

// DIF radix-2 length-32 FFT on packed planes: natural in, bit-reversed out.
template<bool INV>
__device__ __forceinline__ void pfft32_dif(P R[32], P I[32]) {
#pragma unroll
    for (int s = 0; s < 5; s++) {
        const int len = 32 >> s, half = len >> 1;
#pragma unroll
        for (int g = 0; g < 32; g += len)
#pragma unroll
            for (int j = 0; j < half; j++) {
                const int a = g + j, b = a + half;
                P dr = psub(R[a], R[b]), di = psub(I[a], I[b]);
                R[a] = padd(R[a], R[b]); I[a] = padd(I[a], I[b]);
                prot<INV>(j << s, dr, di, R[b], I[b]);
            }
    }
}

// DIT radix-2 length-32 inverse FFT: bit-reversed in, natural out.
__device__ __forceinline__ void pfft32_dit_inv(P R[32], P I[32]) {
#pragma unroll
    for (int s = 4; s >= 0; s--) {
        const int len = 32 >> s, half = len >> 1;
#pragma unroll
        for (int g = 0; g < 32; g += len)
#pragma unroll
            for (int j = 0; j < half; j++) {
                const int a = g + j, b = a + half;
                P tr, ti;
                prot<true>(j << s, R[b], I[b], tr, ti);
                R[b] = psub(R[a], tr); I[b] = psub(I[a], ti);
                R[a] = padd(R[a], tr); I[a] = padd(I[a], ti);
            }
    }
}

// ---------------- scalar versions (init kernel only) ----------------

template<bool INV>
__device__ __forceinline__ void rot_s(int t, float dr, float di, float& xr, float& xi) {
    if (t == 0)      { xr = dr; xi = di; }
    else if (t == 8) {
        if (!INV) { xr = di;  xi = -dr; }
        else      { xr = -di; xi =  dr; }
    } else {
        float c = twc(t), s = tws(t);
        if (!INV) { xr = fmaf(dr, c,  di * s); xi = fmaf(di, c, -dr * s); }
        else      { xr = fmaf(dr, c, -di * s); xi = fmaf(di, c,  dr * s); }
    }
}
template<bool INV>
__device__ __forceinline__ void fft32_dif_s(float zr[32], float zi[32]) {
#pragma unroll
    for (int s = 0; s < 5; s++) {
        const int len = 32 >> s, half = len >> 1;
#pragma unroll
        for (int g = 0; g < 32; g += len)
#pragma unroll
            for (int j = 0; j < half; j++) {
                const int a = g + j, b = a + half;
                float dr = zr[a] - zr[b], di = zi[a] - zi[b];
                zr[a] += zr[b]; zi[a] += zi[b];
                rot_s<INV>(j << s, dr, di, zr[b], zi[b]);
            }
    }
}

// ---------------- init kernels ----------------

__global__ void k_mtw() {
    int i = blockIdx.x * blockDim.x + threadIdx.x;   // <<<4,256>>> -> 1024
    int k = i >> 5, lane = i & 31;
    int prod = (k * lane) & 1023;
    float s, c;
    sincospif((float)prod * (1.0f / 512.0f), &s, &c);
    g_mtw[i] = make_float2(c, -s);                   // e^{-2pi*i*k*lane/1024}
}

__global__ void k_wc(const float* __restrict__ wv) {
    __shared__ float2 B[32 * 33];
    const int lane = threadIdx.x;
    float zr[32], zi[32];
#pragma unroll
    for (int i = 0; i < 32; i++) { zr[i] = wv[32 * i + lane]; zi[i] = 0.0f; }

    fft32_dif_s<false>(zr, zi);                    // over n1; result at br5(k1)
    B[lane * 33 + 0] = make_float2(zr[0], zi[0]);
#pragma unroll
    for (int k1 = 1; k1 < 32; k1++) {              // mid twiddle + transpose store
        const int r = br5(k1);
        float2 t = g_mtw[(k1 << 5) + lane];
        float tr = fmaf(zr[r], t.x, -zi[r] * t.y);
        float ti = fmaf(zi[r], t.x,  zr[r] * t.y);
        B[lane * 33 + k1] = make_float2(tr, ti);
    }
    __syncwarp();
#pragma unroll
    for (int n2 = 0; n2 < 32; n2++) {
        float2 v = B[n2 * 33 + lane];
        zr[n2] = v.x; zi[n2] = v.y;
    }
    fft32_dif_s<false>(zr, zi);                    // over n2; result at br5(k2)
#pragma unroll
    for (int m = 0; m < 32; m++)
        g_wc[(lane << 5) + m] = make_float2(zr[m] * (1.0f / 1024.0f),
                                            zi[m] * (-1.0f / 1024.0f));
}

// ---------------- main kernel ----------------

__global__ void __launch_bounds__(TPB, 2) k_main(const float* __restrict__ x,
                                                 float* __restrict__ out) {
    // per-warp packed transpose planes: [0] = R-plane, [1] = I-plane
    __shared__ unsigned long long tb[WPB][2][32 * 33];
    const int lane = threadIdx.x & 31;
    const int wid  = threadIdx.x >> 5;
    unsigned long long* BR = tb[wid][0];
    unsigned long long* BI = tb[wid][1];

    const long base = ((long)blockIdx.x * WPB + wid) * 4096;   // 4 tokens
    const float* __restrict__ xa1 = x + base;          // seq1 = xa1 + i*xb1
    const float* __restrict__ xb1 = xa1 + 1024;
    const float* __restrict__ xa2 = xa1 + 2048;        // seq2 = xa2 + i*xb2
    const float* __restrict__ xb2 = xa1 + 3072;

    P R[32], I[32];
#pragma unroll
    for (int i = 0; i < 32; i++) {                     // coalesced 128B per ld
        R[i] = pk(xa1[32 * i + lane], xa2[32 * i + lane]);
        I[i] = pk(xb1[32 * i + lane], xb2[32 * i + lane]);
    }

    // ---- forward: FFT over n1, mid twiddle + transpose, FFT over n2 ----
    pfft32_dif<false>(R, I);                           // result at br5(k1)

    BR[lane * 33 + 0] = R[0].v; BI[lane * 33 + 0] = I[0].v;
#pragma unroll
    for (int k1 = 1; k1 < 32; k1++) {                  // * e^{-2pi*i*lane*k1/1024}
        const int r = br5(k1);
        float2 t = g_mtw[(k1 << 5) + lane];            // (c, -s)
        P tr = pfma(R[r], pbc(t.x), pmul(I[r], pbc(-t.y)));
        P ti = pfma(I[r], pbc(t.x), pmul(R[r], pbc( t.y)));
        BR[lane * 33 + k1] = tr.v; BI[lane * 33 + k1] = ti.v;
    }
    __syncwarp();
#pragma unroll
    for (int n2 = 0; n2 < 32; n2++) {                  // transpose: lane := k1
        R[n2].v = BR[n2 * 33 + lane];
        I[n2].v = BI[n2 * 33 + lane];
    }
    pfft32_dif<false>(R, I);                           // over n2; at br5(k2)

    // ---- pointwise: Z * conj(W)/N (layout matches k_wc) ----
    const float4* wc4 = (const float4*)(g_wc + (lane << 5));
#pragma unroll
    for (int m = 0; m < 16; m++) {
        float4 v = wc4[m];
        {
            P a = R[2 * m], b = I[2 * m];
            R[2 * m] = pfma(a, pbc(v.x), pmul(b, pbc(-v.y)));
            I[2 * m] = pfma(b, pbc(v.x), pmul(a, pbc( v.y)));
        }
        {
            P a = R[2 * m + 1], b = I[2 * m + 1];
            R[2 * m + 1] = pfma(a, pbc(v.z), pmul(b, pbc(-v.w)));
            I[2 * m + 1] = pfma(b, pbc(v.z), pmul(a, pbc( v.w)));
        }
    }

    // ---- inverse: IFFT over k2, conj mid twiddle + transpose, IFFT over k1 ----
    pfft32_dit_inv(R, I);                              // br in -> natural n2

    __syncwarp();                                      // transpose-1 loads done
    BR[lane * 33 + 0] = R[0].v; BI[lane * 33 + 0] = I[0].v;
#pragma unroll
    for (int n2 = 1; n2 < 32; n2++) {                  // * e^{+2pi*i*n2*lane/1024}
        float2 t = g_mtw[(n2 << 5) + lane];            // conj of (c,-s)
        P tr = pfma(R[n2], pbc(t.x), pmul(I[n2], pbc( t.y)));
        P ti = pfma(I[n2], pbc(t.x), pmul(R[n2], pbc(-t.y)));
        BR[lane * 33 + n2] = tr.v; BI[lane * 33 + n2] = ti.v;
    }
    __syncwarp();
#pragma unroll
    for (int k1 = 0; k1 < 32; k1++) {                  // transpose: lane := n2
        R[k1].v = BR[k1 * 33 + lane];
        I[k1].v = BI[k1 * 33 + lane];
    }
    pfft32_dif<true>(R, I);                            // inverse over k1 -> br5(n1)

    // ---- epilogue: mm at (lane=n2, reg br5(n1)) => token index 32*n1+lane ----
    float* __restrict__ oa1 = out + base;
    float* __restrict__ ob1 = oa1 + 1024;
    float* __restrict__ oa2 = oa1 + 2048;
    float* __restrict__ ob2 = oa1 + 3072;
#pragma unroll
    for (int n1 = 0; n1 < 32; n1++) {
        const int r = br5(n1);
        const int idx = 32 * n1 + lane;
        float ma1, ma2, mb1, mb2;
        upk(R[r], ma1, ma2);
        upk(I[r], mb1, mb2);
        float v1 = xa1[idx], v2 = xb1[idx], v3 = xa2[idx], v4 = xb2[idx];
        oa1[idx] = fmaf(ma1, v1, ma1 + v1);            // mm*x + mm + x
        ob1[idx] = fmaf(mb1, v2, mb1 + v2);
        oa2[idx] = fmaf(ma2, v3, ma2 + v3);
        ob2[idx] = fmaf(mb2, v4, mb2 + v4);
    }
}

extern "C" void kernel_launch(void* const* d_in, const int* in_sizes, int n_in,
                              void* d_out, int out_size) {
    const float* x = (const float*)d_in[0];   // [65536, 1024] fp32
    const float* w = (const float*)d_in[1];   // [1024] fp32
    float* out = (float*)d_out;

    k_mtw<<<4, 256>>>();
    k_wc<<<1, 32>>>(w);
    k_main<<<NTOK / 4 / WPB, TPB>>>(x, out);
}

// round 9
// speedup vs baseline: 1.3467x; 1.3467x over previous
#include <cuda_runtime.h>

// circ_layer: out = mm*x + mm + x, mm[b,i] = sum_j x[b,j] * w[(j-i) mod 1024]
// = circular correlation => IDFT( FFT(x_row) * conj(FFT(w)) ), fp32.
//
// Four-step FFT (1024 = 32x32), one warp per TWO tokens (z = xa + i*xb).
// Each complex value lives in ONE 64-bit register pair (re,im); butterfly
// add/sub use packed add/fma.rn.f32x2 (half the instructions), rotations
// unpack to scalars (immediate-constant FMAs) and repack. Register-neutral
// vs the scalar version. Two 32x32 smem transposes; no __syncthreads.

static constexpr int WPB  = 4;            // warps per block
static constexpr int TPB  = WPB * 32;
static constexpr int NTOK = 65536;

__device__ __align__(16) float2 g_wc[1024];    // conj(FFT(w))/N, pipeline layout
__device__ __align__(16) float2 g_mtw[1024];   // T[k*32+lane] = e^{-2pi*i*k*lane/1024}

__device__ __forceinline__ int br5(int x) {
    return ((x & 1) << 4) | ((x & 2) << 2) | (x & 4) | ((x & 8) >> 2) | ((x & 16) >> 4);
}

__device__ __forceinline__ float twc(int t) {
    constexpr float C[16] = {
        1.0f,                   0.9807852804032304f,  0.9238795325112867f,  0.8314696123025452f,
        0.7071067811865476f,    0.5555702330196022f,  0.3826834323650898f,  0.1950903220161283f,
        0.0f,                  -0.1950903220161283f, -0.3826834323650898f, -0.5555702330196022f,
       -0.7071067811865476f,   -0.8314696123025452f, -0.9238795325112867f, -0.9807852804032304f };
    return C[t];
}
__device__ __forceinline__ float tws(int t) {
    constexpr float S[16] = {
        0.0f,                   0.1950903220161283f,  0.3826834323650898f,  0.5555702330196022f,
        0.7071067811865476f,    0.8314696123025452f,  0.9238795325112867f,  0.9807852804032304f,
        1.0f,                   0.9807852804032304f,  0.9238795325112867f,  0.8314696123025452f,
        0.7071067811865476f,    0.5555702330196022f,  0.3826834323650898f,  0.1950903220161283f };
    return S[t];
}

// ---------------- packed (re,im) complex in one 64-bit value ----------------

struct P { unsigned long long v; };

__device__ __forceinline__ P pk(float re, float im) {
    P r; asm("mov.b64 %0, {%1, %2};" : "=l"(r.v) : "f"(re), "f"(im)); return r;
}
__device__ __forceinline__ void upk(P a, float& re, float& im) {
    asm("mov.b64 {%0, %1}, %2;" : "=f"(re), "=f"(im) : "l"(a.v));
}
__device__ __forceinline__ P padd(P a, P b) {           // complex add (2 lanes)
    P r; asm("add.rn.f32x2 %0, %1, %2;" : "=l"(r.v) : "l"(a.v), "l"(b.v)); return r;
}
__device__ __forceinline__ P pfma(P a, P b, P c) {      // a*b + c elementwise
    P r; asm("fma.rn.f32x2 %0, %1, %2, %3;" : "=l"(r.v) : "l"(a.v), "l"(b.v), "l"(c.v)); return r;
}
__device__ __forceinline__ P pneg1() {                  // (-1, -1); CSE'd by ptxas
    return pk(-1.0f, -1.0f);
}
__device__ __forceinline__ P psub(P a, P b) {           // a - b  (b*-1 + a)
    return pfma(b, pneg1(), a);
}

// out = d * e^{-+2*pi*i*t/32}; scalar rotation on unpacked halves.
template<bool INV>
__device__ __forceinline__ P prot(int t, P d) {
    if (t == 0) return d;
    float r, i;
    upk(d, r, i);
    if (t == 8) {
        if (!INV) return pk(i, -r);       // * (-i)
        else      return pk(-i, r);       // * (+i)
    }
    const float c = twc(t), s = tws(t);
    if (!INV) return pk(fmaf(r, c,  i * s), fmaf(i, c, -r * s));
    else      return pk(fmaf(r, c, -i * s), fmaf(i, c,  r * s));
}

// DIF radix-2 length-32 FFT: natural in, bit-reversed out.
template<bool INV>
__device__ __forceinline__ void pfft32_dif(P Z[32]) {
#pragma unroll
    for (int s = 0; s < 5; s++) {
        const int len = 32 >> s, half = len >> 1;
#pragma unroll
        for (int g = 0; g < 32; g += len)
#pragma unroll
            for (int j = 0; j < half; j++) {
                const int a = g + j, b = a + half;
                P d = psub(Z[a], Z[b]);
                Z[a] = padd(Z[a], Z[b]);
                Z[b] = prot<INV>(j << s, d);
            }
    }
}

// DIT radix-2 length-32 inverse FFT: bit-reversed in, natural out.
__device__ __forceinline__ void pfft32_dit_inv(P Z[32]) {
#pragma unroll
    for (int s = 4; s >= 0; s--) {
        const int len = 32 >> s, half = len >> 1;
#pragma unroll
        for (int g = 0; g < 32; g += len)
#pragma unroll
            for (int j = 0; j < half; j++) {
                const int a = g + j, b = a + half;
                P t = prot<true>(j << s, Z[b]);
                Z[b] = psub(Z[a], t);
                Z[a] = padd(Z[a], t);
            }
    }
}

// ---------------- scalar FFT (init kernel only) ----------------

template<bool INV>
__device__ __forceinline__ void rot_s(int t, float dr, float di, float& xr, float& xi) {
    if (t == 0)      { xr = dr; xi = di; }
    else if (t == 8) {
        if (!INV) { xr = di;  xi = -dr; }
        else      { xr = -di; xi =  dr; }
    } else {
        float c = twc(t), s = tws(t);
        if (!INV) { xr = fmaf(dr, c,  di * s); xi = fmaf(di, c, -dr * s); }
        else      { xr = fmaf(dr, c, -di * s); xi = fmaf(di, c,  dr * s); }
    }
}
template<bool INV>
__device__ __forceinline__ void fft32_dif_s(float zr[32], float zi[32]) {
#pragma unroll
    for (int s = 0; s < 5; s++) {
        const int len = 32 >> s, half = len >> 1;
#pragma unroll
        for (int g = 0; g < 32; g += len)
#pragma unroll
            for (int j = 0; j < half; j++) {
                const int a = g + j, b = a + half;
                float dr = zr[a] - zr[b], di = zi[a] - zi[b];
                zr[a] += zr[b]; zi[a] += zi[b];
                rot_s<INV>(j << s, dr, di, zr[b], zi[b]);
            }
    }
}

// ---------------- init kernels ----------------

__global__ void k_mtw() {
    int i = blockIdx.x * blockDim.x + threadIdx.x;   // <<<4,256>>> -> 1024
    int k = i >> 5, lane = i & 31;
    int prod = (k * lane) & 1023;
    float s, c;
    sincospif((float)prod * (1.0f / 512.0f), &s, &c);
    g_mtw[i] = make_float2(c, -s);                   // e^{-2pi*i*k*lane/1024}
}

__global__ void k_wc(const float* __restrict__ wv) {
    __shared__ float2 B[32 * 33];
    const int lane = threadIdx.x;
    float zr[32], zi[32];
#pragma unroll
    for (int i = 0; i < 32; i++) { zr[i] = wv[32 * i + lane]; zi[i] = 0.0f; }

    fft32_dif_s<false>(zr, zi);                    // over n1; result at br5(k1)
    B[lane * 33 + 0] = make_float2(zr[0], zi[0]);
#pragma unroll
    for (int k1 = 1; k1 < 32; k1++) {              // mid twiddle + transpose store
        const int r = br5(k1);
        float2 t = g_mtw[(k1 << 5) + lane];
        float tr = fmaf(zr[r], t.x, -zi[r] * t.y);
        float ti = fmaf(zi[r], t.x,  zr[r] * t.y);
        B[lane * 33 + k1] = make_float2(tr, ti);
    }
    __syncwarp();
#pragma unroll
    for (int n2 = 0; n2 < 32; n2++) {
        float2 v = B[n2 * 33 + lane];
        zr[n2] = v.x; zi[n2] = v.y;
    }
    fft32_dif_s<false>(zr, zi);                    // over n2; result at br5(k2)
#pragma unroll
    for (int m = 0; m < 32; m++)
        g_wc[(lane << 5) + m] = make_float2(zr[m] * (1.0f / 1024.0f),
                                            zi[m] * (-1.0f / 1024.0f));
}

// ---------------- main kernel ----------------

__global__ void __launch_bounds__(TPB, 3) k_main(const float* __restrict__ x,
                                                 float* __restrict__ out) {
    __shared__ unsigned long long tb[WPB][32 * 33];   // per-warp (re,im) plane
    const int lane = threadIdx.x & 31;
    const int wid  = threadIdx.x >> 5;
    unsigned long long* B = tb[wid];

    const long base = ((long)blockIdx.x * WPB + wid) * 2048;   // 2 tokens
    const float* __restrict__ xa = x + base;
    const float* __restrict__ xb = xa + 1024;

    P Z[32];
#pragma unroll
    for (int i = 0; i < 32; i++)                   // coalesced 128B per ld
        Z[i] = pk(xa[32 * i + lane], xb[32 * i + lane]);

    // ---- forward: FFT over n1, mid twiddle + transpose, FFT over n2 ----
    pfft32_dif<false>(Z);                          // result at br5(k1)

    B[lane * 33 + 0] = Z[0].v;
#pragma unroll
    for (int k1 = 1; k1 < 32; k1++) {              // * e^{-2pi*i*lane*k1/1024}
        const int r = br5(k1);
        float2 t = g_mtw[(k1 << 5) + lane];        // (c, -s)
        float zr, zi;
        upk(Z[r], zr, zi);
        float tr = fmaf(zr, t.x, -zi * t.y);
        float ti = fmaf(zi, t.x,  zr * t.y);
        B[lane * 33 + k1] = pk(tr, ti).v;
    }
    __syncwarp();
#pragma unroll
    for (int n2 = 0; n2 < 32; n2++)                // transpose: lane := k1
        Z[n2].v = B[n2 * 33 + lane];
    pfft32_dif<false>(Z);                          // over n2; at br5(k2)

    // ---- pointwise: Z * conj(W)/N (layout matches k_wc) ----
    const float4* wc4 = (const float4*)(g_wc + (lane << 5));
#pragma unroll
    for (int m = 0; m < 16; m++) {
        float4 v = wc4[m];
        {
            float a, b;
            upk(Z[2 * m], a, b);
            Z[2 * m] = pk(fmaf(a, v.x, -b * v.y), fmaf(a, v.y, b * v.x));
        }
        {
            float a, b;
            upk(Z[2 * m + 1], a, b);
            Z[2 * m + 1] = pk(fmaf(a, v.z, -b * v.w), fmaf(a, v.w, b * v.z));
        }
    }

    // ---- inverse: IFFT over k2, conj mid twiddle + transpose, IFFT over k1 ----
    pfft32_dit_inv(Z);                             // br in -> natural n2

    __syncwarp();                                  // transpose-1 loads done
    B[lane * 33 + 0] = Z[0].v;
#pragma unroll
    for (int n2 = 1; n2 < 32; n2++) {              // * e^{+2pi*i*n2*lane/1024}
        float2 t = g_mtw[(n2 << 5) + lane];        // conj of (c,-s)
        float zr, zi;
        upk(Z[n2], zr, zi);
        float tr = fmaf(zr, t.x,  zi * t.y);
        float ti = fmaf(zi, t.x, -zr * t.y);
        B[lane * 33 + n2] = pk(tr, ti).v;
    }
    __syncwarp();
#pragma unroll
    for (int k1 = 0; k1 < 32; k1++)                // transpose: lane := n2
        Z[k1].v = B[k1 * 33 + lane];
    pfft32_dif<true>(Z);                           // inverse over k1 -> br5(n1)

    // ---- epilogue: mm at (lane=n2, reg br5(n1)) => token index 32*n1+lane ----
    float* __restrict__ oa = out + base;
    float* __restrict__ ob = oa + 1024;
#pragma unroll
    for (int n1 = 0; n1 < 32; n1++) {
        const int r = br5(n1);
        const int idx = 32 * n1 + lane;
        float ma, mb;
        upk(Z[r], ma, mb);
        float xav = xa[idx], xbv = xb[idx];        // reload (L1-hot)
        oa[idx] = fmaf(ma, xav, ma + xav);         // mm*x + mm + x
        ob[idx] = fmaf(mb, xbv, mb + xbv);
    }
}

extern "C" void kernel_launch(void* const* d_in, const int* in_sizes, int n_in,
                              void* d_out, int out_size) {
    const float* x = (const float*)d_in[0];   // [65536, 1024] fp32
    const float* w = (const float*)d_in[1];   // [1024] fp32
    float* out = (float*)d_out;

    k_mtw<<<4, 256>>>();
    k_wc<<<1, 32>>>(w);
    k_main<<<NTOK / 2 / WPB, TPB>>>(x, out);
}